// round 5
// baseline (speedup 1.0000x reference)
#include <cuda_runtime.h>
#include <math.h>

#define NB 8
#define NS 2048
#define ND 256
#define NE 256
static constexpr float kScale = 0.125f;  // 1/sqrt(64), per reference source

typedef unsigned long long u64;

// ---- packed f32x2 helpers (SASS FFMA2/FMUL2 — ptxas never emits these) ----
__device__ __forceinline__ u64 pack2(float x, float y) {
    u64 r;
    asm("mov.b64 %0, {%1, %2};" : "=l"(r) : "r"(__float_as_uint(x)), "r"(__float_as_uint(y)));
    return r;
}
__device__ __forceinline__ void unpack2(u64 v, float& x, float& y) {
    unsigned lo, hi;
    asm("mov.b64 {%0, %1}, %2;" : "=r"(lo), "=r"(hi) : "l"(v));
    x = __uint_as_float(lo);
    y = __uint_as_float(hi);
}
__device__ __forceinline__ void ffma2(u64& d, u64 a, u64 b) {
    asm("fma.rn.f32x2 %0, %1, %2, %0;" : "+l"(d) : "l"(a), "l"(b));
}
__device__ __forceinline__ void fmul2(u64& d, u64 a) {
    asm("mul.rn.f32x2 %0, %0, %1;" : "+l"(d) : "l"(a));
}

// ---- cp.async primitives with explicit group control ----
__device__ __forceinline__ void cp16(void* smem_dst, const void* gmem_src) {
    unsigned dst = (unsigned)__cvta_generic_to_shared(smem_dst);
    asm volatile("cp.async.cg.shared.global [%0], [%1], 16;" :: "r"(dst), "l"(gmem_src));
}
__device__ __forceinline__ void cp_commit() {
    asm volatile("cp.async.commit_group;" ::: "memory");
}
__device__ __forceinline__ void cp_wait0() {
    asm volatile("cp.async.wait_group 0;" ::: "memory");
}
__device__ __forceinline__ void cp_wait1() {
    asm volatile("cp.async.wait_group 1;" ::: "memory");
}

// Scratch for Q, K, V projections (allocation-free: __device__ globals)
__device__ float g_Q[NB * NS * NE];
__device__ float g_K[NB * NS * NE];
__device__ float g_V[NB * NS * NE];

// ---------------------------------------------------------------------------
// QKV projection: C_p = X(16384x256) @ W_p(256x256), p = blockIdx.z in {0,1,2}
// ---------------------------------------------------------------------------
__global__ __launch_bounds__(256) void qkv_kernel(const float* __restrict__ x,
                                                  const float* __restrict__ w) {
    __shared__ __align__(16) float As[64][20];
    __shared__ __align__(16) float Bs[16][68];

    const int p = blockIdx.z;
    const float* W = w + (size_t)p * ND * NE;
    float* out = (p == 0) ? g_Q : ((p == 1) ? g_K : g_V);
    const int row0 = blockIdx.x * 64;
    const int col0 = blockIdx.y * 64;
    const int tid = threadIdx.x;
    const int tx = tid & 15;
    const int ty = tid >> 4;

    ulonglong2 acc[4];
#pragma unroll
    for (int i = 0; i < 4; i++) { acc[i].x = 0ull; acc[i].y = 0ull; }

    for (int k0 = 0; k0 < ND; k0 += 16) {
        {
            int r = tid >> 2;
            int c = (tid & 3) << 2;
            cp16(&As[r][c], &x[(size_t)(row0 + r) * ND + k0 + c]);
        }
        {
            int r = tid >> 4;
            int c = (tid & 15) << 2;
            cp16(&Bs[r][c], &W[(size_t)(k0 + r) * NE + col0 + c]);
        }
        cp_commit();
        cp_wait0();
        __syncthreads();
#pragma unroll
        for (int kk = 0; kk < 16; kk++) {
            ulonglong2 bv = *(const ulonglong2*)&Bs[kk][tx << 2];
#pragma unroll
            for (int i = 0; i < 4; i++) {
                float a = As[(ty << 2) + i][kk];
                u64 ap = pack2(a, a);
                ffma2(acc[i].x, ap, bv.x);
                ffma2(acc[i].y, ap, bv.y);
            }
        }
        __syncthreads();
    }
#pragma unroll
    for (int i = 0; i < 4; i++) {
        *(ulonglong2*)&out[(size_t)(row0 + (ty << 2) + i) * NE + col0 + (tx << 2)] = acc[i];
    }
}

// ---------------------------------------------------------------------------
// Flash-attention, 512 threads. Warp wy owns query rows wy+16i (i<4); lane tx
// owns key cols tx+32j (j<2) and output cols tx*4+128*cc (cc<2).
// K/V tiles are software-pipelined through single buffers via cp.async groups:
//   loop top:  wait_group 1  -> K(t) resident    (V(t) still in flight)
//   mid tile:  wait_group 0  -> V(t) resident; K(t+1) issued, overlaps PV
//   loop end:  V(t+1) issued, overlaps next QK
// Inner loops register-double-buffer their LDS (prefetch reads 16B pad, safe).
// ---------------------------------------------------------------------------
__global__ __launch_bounds__(512, 1) void attn_kernel(const int* __restrict__ mask,
                                                      float* __restrict__ out) {
    extern __shared__ float sm[];
    float* Qs = sm;               // [64][260]
    float* Ks = Qs + 64 * 260;    // [64][260]
    float* Vs = Ks + 64 * 260;    // [64][260]
    float* Ps = Vs + 64 * 260;    // [64][68]
    float* rs = Ps + 64 * 68;     // [64]

    const int b  = blockIdx.y;
    const int q0 = blockIdx.x * 64;
    const float* __restrict__ Qg = g_Q + (size_t)b * NS * NE;
    const float* __restrict__ Kg = g_K + (size_t)b * NS * NE;
    const float* __restrict__ Vg = g_V + (size_t)b * NS * NE;

    const int tid = threadIdx.x;
    const int tx = tid & 31;   // lane
    const int wy = tid >> 5;   // warp id (query row group)

    // --- preload: Q (group), K0 (group), V0 (group); rs via plain STS ---
    for (int i = tid; i < 64 * 64; i += 512) {
        int r = i >> 6, c = (i & 63) << 2;
        cp16(&Qs[r * 260 + c], &Qg[(size_t)(q0 + r) * NE + c]);
    }
    cp_commit();
    for (int i = tid; i < 64 * 64; i += 512) {
        int r = i >> 6, c = (i & 63) << 2;
        cp16(&Ks[r * 260 + c], &Kg[(size_t)r * NE + c]);
    }
    cp_commit();
    for (int i = tid; i < 64 * 64; i += 512) {
        int r = i >> 6, c = (i & 63) << 2;
        cp16(&Vs[r * 260 + c], &Vg[(size_t)r * NE + c]);
    }
    cp_commit();
    if (tid < 64) rs[tid] = kScale * (float)mask[b * NS + q0 + tid];
    __syncthreads();  // rs visible (cp groups still in flight)

    int qr[4];
    float rscale[4];
#pragma unroll
    for (int i = 0; i < 4; i++) { qr[i] = wy + 16 * i; rscale[i] = rs[qr[i]]; }

    ulonglong2 O2[4][2];
#pragma unroll
    for (int i = 0; i < 4; i++)
#pragma unroll
        for (int cc = 0; cc < 2; cc++) { O2[i][cc].x = 0ull; O2[i][cc].y = 0ull; }

    float m_run[4], l_run[4];
#pragma unroll
    for (int i = 0; i < 4; i++) { m_run[i] = -INFINITY; l_run[i] = 0.f; }

    for (int kt = 0; kt < NS / 64; kt++) {
        cp_wait1();        // K(kt) resident (thread-local), V(kt) may be in flight
        __syncthreads();   // all threads' K parts visible

        // ---- QK with register double-buffered LDS ----
        u64 s2[4][2];
#pragma unroll
        for (int i = 0; i < 4; i++)
#pragma unroll
            for (int j = 0; j < 2; j++) s2[i][j] = 0ull;

        ulonglong2 qn[4], kn[2];
#pragma unroll
        for (int i = 0; i < 4; i++) qn[i] = *(const ulonglong2*)&Qs[qr[i] * 260];
        kn[0] = *(const ulonglong2*)&Ks[tx * 260];
        kn[1] = *(const ulonglong2*)&Ks[(tx + 32) * 260];

#pragma unroll 8
        for (int e = 0; e < NE; e += 4) {
            ulonglong2 qc[4], kc[2];
#pragma unroll
            for (int i = 0; i < 4; i++) qc[i] = qn[i];
            kc[0] = kn[0];
            kc[1] = kn[1];
            // prefetch next step (e=252 reads the 4-float row pad: in-bounds)
#pragma unroll
            for (int i = 0; i < 4; i++) qn[i] = *(const ulonglong2*)&Qs[qr[i] * 260 + e + 4];
            kn[0] = *(const ulonglong2*)&Ks[tx * 260 + e + 4];
            kn[1] = *(const ulonglong2*)&Ks[(tx + 32) * 260 + e + 4];
#pragma unroll
            for (int i = 0; i < 4; i++)
#pragma unroll
                for (int j = 0; j < 2; j++) {
                    ffma2(s2[i][j], qc[i].x, kc[j].x);
                    ffma2(s2[i][j], qc[i].y, kc[j].y);
                }
        }

        // ---- softmax (full-warp reductions) ----
        float p[4][2];
#pragma unroll
        for (int i = 0; i < 4; i++) {
            float s[2];
#pragma unroll
            for (int j = 0; j < 2; j++) {
                float lo, hi;
                unpack2(s2[i][j], lo, hi);
                s[j] = (lo + hi) * rscale[i];
            }
            float mt = fmaxf(s[0], s[1]);
            mt = fmaxf(mt, __shfl_xor_sync(0xffffffffu, mt, 16));
            mt = fmaxf(mt, __shfl_xor_sync(0xffffffffu, mt, 8));
            mt = fmaxf(mt, __shfl_xor_sync(0xffffffffu, mt, 4));
            mt = fmaxf(mt, __shfl_xor_sync(0xffffffffu, mt, 2));
            mt = fmaxf(mt, __shfl_xor_sync(0xffffffffu, mt, 1));
            float mn = fmaxf(m_run[i], mt);

            float sum = 0.f;
#pragma unroll
            for (int j = 0; j < 2; j++) {
                p[i][j] = __expf(s[j] - mn);
                sum += p[i][j];
            }
            sum += __shfl_xor_sync(0xffffffffu, sum, 16);
            sum += __shfl_xor_sync(0xffffffffu, sum, 8);
            sum += __shfl_xor_sync(0xffffffffu, sum, 4);
            sum += __shfl_xor_sync(0xffffffffu, sum, 2);
            sum += __shfl_xor_sync(0xffffffffu, sum, 1);

            float alpha = __expf(m_run[i] - mn);  // 0 on first tile
            l_run[i] = l_run[i] * alpha + sum;
            m_run[i] = mn;
            u64 a2 = pack2(alpha, alpha);
#pragma unroll
            for (int cc = 0; cc < 2; cc++) {
                fmul2(O2[i][cc].x, a2);
                fmul2(O2[i][cc].y, a2);
            }
        }

        // P rows wy+16i produced & consumed by warp wy only
#pragma unroll
        for (int i = 0; i < 4; i++)
#pragma unroll
            for (int j = 0; j < 2; j++) Ps[qr[i] * 68 + tx + 32 * j] = p[i][j];
        __syncwarp();

        cp_wait0();        // V(kt) resident (thread-local)
        __syncthreads();   // all V parts visible AND all warps done reading Ks

        // prefetch K(kt+1) into Ks — overlaps the PV phase
        if (kt + 1 < NS / 64) {
            const float* Kn = Kg + (size_t)(kt + 1) * 64 * NE;
            for (int i = tid; i < 64 * 64; i += 512) {
                int r = i >> 6, c = (i & 63) << 2;
                cp16(&Ks[r * 260 + c], &Kn[(size_t)r * NE + c]);
            }
            cp_commit();
        }

        // ---- PV with register double-buffered LDS ----
        ulonglong2 vn[2];
        vn[0] = *(const ulonglong2*)&Vs[(tx << 2)];
        vn[1] = *(const ulonglong2*)&Vs[(tx << 2) + 128];
        float pn[4];
#pragma unroll
        for (int i = 0; i < 4; i++) pn[i] = Ps[qr[i] * 68];

#pragma unroll 8
        for (int j = 0; j < 64; j++) {
            ulonglong2 vc[2];
            vc[0] = vn[0];
            vc[1] = vn[1];
            u64 pp[4];
#pragma unroll
            for (int i = 0; i < 4; i++) pp[i] = pack2(pn[i], pn[i]);
            // prefetch next step (j=63 reads into Ps region / row pad: in-bounds)
            vn[0] = *(const ulonglong2*)&Vs[(j + 1) * 260 + (tx << 2)];
            vn[1] = *(const ulonglong2*)&Vs[(j + 1) * 260 + (tx << 2) + 128];
#pragma unroll
            for (int i = 0; i < 4; i++) pn[i] = Ps[qr[i] * 68 + j + 1];
#pragma unroll
            for (int i = 0; i < 4; i++)
#pragma unroll
                for (int cc = 0; cc < 2; cc++) {
                    ffma2(O2[i][cc].x, pp[i], vc[cc].x);
                    ffma2(O2[i][cc].y, pp[i], vc[cc].y);
                }
        }
        __syncthreads();   // all warps done reading Vs

        // prefetch V(kt+1) into Vs — overlaps next tile's QK phase
        if (kt + 1 < NS / 64) {
            const float* Vn = Vg + (size_t)(kt + 1) * 64 * NE;
            for (int i = tid; i < 64 * 64; i += 512) {
                int r = i >> 6, c = (i & 63) << 2;
                cp16(&Vs[r * 260 + c], &Vn[(size_t)r * NE + c]);
            }
            cp_commit();
        }
    }

    // Epilogue: normalize (packed) and store 16B per (i,cc)
#pragma unroll
    for (int i = 0; i < 4; i++) {
        float inv = 1.0f / l_run[i];
        u64 inv2 = pack2(inv, inv);
#pragma unroll
        for (int cc = 0; cc < 2; cc++) {
            fmul2(O2[i][cc].x, inv2);
            fmul2(O2[i][cc].y, inv2);
            *(ulonglong2*)&out[(size_t)(b * NS + q0 + qr[i]) * NE + (tx << 2) + 128 * cc] =
                O2[i][cc];
        }
    }
}

// ---------------------------------------------------------------------------
extern "C" void kernel_launch(void* const* d_in, const int* in_sizes, int n_in,
                              void* d_out, int out_size) {
    (void)in_sizes; (void)n_in; (void)out_size;
    const float* x    = (const float*)d_in[0];  // [8, 2048, 256] f32
    const float* w    = (const float*)d_in[1];  // [3, 256, 256]  f32
    const int*   mask = (const int*)d_in[2];    // [8, 2048]      i32
    float* out = (float*)d_out;                 // [8, 2048, 256] f32

    dim3 g1((NB * NS) / 64, NE / 64, 3);
    qkv_kernel<<<g1, 256>>>(x, w);

    const size_t smem = (size_t)(3 * 64 * 260 + 64 * 68 + 64) * sizeof(float);  // 217,344 B
    cudaFuncSetAttribute(attn_kernel, cudaFuncAttributeMaxDynamicSharedMemorySize,
                         (int)smem);
    dim3 g2(NS / 64, NB);
    attn_kernel<<<g2, 512, smem>>>(mask, out);
}

// round 6
// speedup vs baseline: 1.1487x; 1.1487x over previous
#include <cuda_runtime.h>
#include <math.h>

#define NB 8
#define NS 2048
#define ND 256
#define NE 256
static constexpr float kScale = 0.125f;  // 1/sqrt(64), per reference source

typedef unsigned long long u64;

// ---- packed f32x2 helpers (SASS FFMA2/FMUL2 — ptxas never emits these) ----
__device__ __forceinline__ u64 pack2(float x, float y) {
    u64 r;
    asm("mov.b64 %0, {%1, %2};" : "=l"(r) : "r"(__float_as_uint(x)), "r"(__float_as_uint(y)));
    return r;
}
__device__ __forceinline__ void unpack2(u64 v, float& x, float& y) {
    unsigned lo, hi;
    asm("mov.b64 {%0, %1}, %2;" : "=r"(lo), "=r"(hi) : "l"(v));
    x = __uint_as_float(lo);
    y = __uint_as_float(hi);
}
__device__ __forceinline__ void ffma2(u64& d, u64 a, u64 b) {
    asm("fma.rn.f32x2 %0, %1, %2, %0;" : "+l"(d) : "l"(a), "l"(b));
}
__device__ __forceinline__ void fmul2(u64& d, u64 a) {
    asm("mul.rn.f32x2 %0, %0, %1;" : "+l"(d) : "l"(a));
}

// ---- cp.async primitives with explicit group control ----
__device__ __forceinline__ void cp16(void* smem_dst, const void* gmem_src) {
    unsigned dst = (unsigned)__cvta_generic_to_shared(smem_dst);
    asm volatile("cp.async.cg.shared.global [%0], [%1], 16;" :: "r"(dst), "l"(gmem_src));
}
__device__ __forceinline__ void cp_commit() {
    asm volatile("cp.async.commit_group;" ::: "memory");
}
__device__ __forceinline__ void cp_wait0() {
    asm volatile("cp.async.wait_group 0;" ::: "memory");
}
__device__ __forceinline__ void cp_wait1() {
    asm volatile("cp.async.wait_group 1;" ::: "memory");
}

// Scratch for Q, K, V projections (allocation-free: __device__ globals)
__device__ float g_Q[NB * NS * NE];
__device__ float g_K[NB * NS * NE];
__device__ float g_V[NB * NS * NE];

// ---------------------------------------------------------------------------
// QKV projection: computes ALL THREE C_p = X @ W_p per block so X is read
// once (memory-bound kernel: traffic 256MB vs 384MB before).
// 64x64 tile, 4x4 micro tile per thread per projection. FFMA2.
// ---------------------------------------------------------------------------
__global__ __launch_bounds__(256) void qkv_kernel(const float* __restrict__ x,
                                                  const float* __restrict__ w) {
    __shared__ __align__(16) float As[64][20];
    __shared__ __align__(16) float Bs[3][16][68];

    const int row0 = blockIdx.x * 64;
    const int col0 = blockIdx.y * 64;
    const int tid = threadIdx.x;
    const int tx = tid & 15;
    const int ty = tid >> 4;

    ulonglong2 acc[3][4];
#pragma unroll
    for (int p = 0; p < 3; p++)
#pragma unroll
        for (int i = 0; i < 4; i++) { acc[p][i].x = 0ull; acc[p][i].y = 0ull; }

    for (int k0 = 0; k0 < ND; k0 += 16) {
        {
            int r = tid >> 2;
            int c = (tid & 3) << 2;
            cp16(&As[r][c], &x[(size_t)(row0 + r) * ND + k0 + c]);
        }
        {
            int r = tid >> 4;
            int c = (tid & 15) << 2;
#pragma unroll
            for (int p = 0; p < 3; p++)
                cp16(&Bs[p][r][c], &w[(size_t)p * ND * NE + (size_t)(k0 + r) * NE + col0 + c]);
        }
        cp_commit();
        cp_wait0();
        __syncthreads();
#pragma unroll
        for (int kk = 0; kk < 16; kk++) {
            ulonglong2 bv[3];
#pragma unroll
            for (int p = 0; p < 3; p++) bv[p] = *(const ulonglong2*)&Bs[p][kk][tx << 2];
#pragma unroll
            for (int i = 0; i < 4; i++) {
                float a = As[(ty << 2) + i][kk];
                u64 ap = pack2(a, a);
#pragma unroll
                for (int p = 0; p < 3; p++) {
                    ffma2(acc[p][i].x, ap, bv[p].x);
                    ffma2(acc[p][i].y, ap, bv[p].y);
                }
            }
        }
        __syncthreads();
    }
#pragma unroll
    for (int i = 0; i < 4; i++) {
        size_t off = (size_t)(row0 + (ty << 2) + i) * NE + col0 + (tx << 2);
        *(ulonglong2*)&g_Q[off] = acc[0][i];
        *(ulonglong2*)&g_K[off] = acc[1][i];
        *(ulonglong2*)&g_V[off] = acc[2][i];
    }
}

// ---------------------------------------------------------------------------
// Flash-attention, 256 threads (8 warps). Warp wy owns query rows wy+8i (i<8);
// lane tx owns key cols tx+32j (j<2) and output cols tx*4+128*cc (cc<2).
// 8 rows per warp halves the K/V smem-crossbar redundancy vs 16 warps
// (crossbar was the measured bottleneck: L1 73.7% vs fma 44%).
// K/V tiles software-pipelined through single buffers via cp.async groups.
// ---------------------------------------------------------------------------
__global__ __launch_bounds__(256, 1) void attn_kernel(const int* __restrict__ mask,
                                                      float* __restrict__ out) {
    extern __shared__ float sm[];
    float* Qs = sm;               // [64][260]
    float* Ks = Qs + 64 * 260;    // [64][260]
    float* Vs = Ks + 64 * 260;    // [64][260]
    float* Ps = Vs + 64 * 260;    // [64][68]
    float* rs = Ps + 64 * 68;     // [64]

    const int b  = blockIdx.y;
    const int q0 = blockIdx.x * 64;
    const float* __restrict__ Qg = g_Q + (size_t)b * NS * NE;
    const float* __restrict__ Kg = g_K + (size_t)b * NS * NE;
    const float* __restrict__ Vg = g_V + (size_t)b * NS * NE;

    const int tid = threadIdx.x;
    const int tx = tid & 31;   // lane
    const int wy = tid >> 5;   // warp id (0..7): query row group

    // --- preload: Q (group), K0 (group), V0 (group); rs via plain STS ---
    for (int i = tid; i < 64 * 64; i += 256) {
        int r = i >> 6, c = (i & 63) << 2;
        cp16(&Qs[r * 260 + c], &Qg[(size_t)(q0 + r) * NE + c]);
    }
    cp_commit();
    for (int i = tid; i < 64 * 64; i += 256) {
        int r = i >> 6, c = (i & 63) << 2;
        cp16(&Ks[r * 260 + c], &Kg[(size_t)r * NE + c]);
    }
    cp_commit();
    for (int i = tid; i < 64 * 64; i += 256) {
        int r = i >> 6, c = (i & 63) << 2;
        cp16(&Vs[r * 260 + c], &Vg[(size_t)r * NE + c]);
    }
    cp_commit();
    if (tid < 64) rs[tid] = kScale * (float)mask[b * NS + q0 + tid];
    __syncthreads();  // rs visible (cp groups still in flight)

    int qr[8];
    float rscale[8];
#pragma unroll
    for (int i = 0; i < 8; i++) { qr[i] = wy + 8 * i; rscale[i] = rs[qr[i]]; }

    ulonglong2 O2[8][2];
#pragma unroll
    for (int i = 0; i < 8; i++)
#pragma unroll
        for (int cc = 0; cc < 2; cc++) { O2[i][cc].x = 0ull; O2[i][cc].y = 0ull; }

    float m_run[8], l_run[8];
#pragma unroll
    for (int i = 0; i < 8; i++) { m_run[i] = -INFINITY; l_run[i] = 0.f; }

    for (int kt = 0; kt < NS / 64; kt++) {
        cp_wait1();        // K(kt) resident (thread-local), V(kt) may be in flight
        __syncthreads();   // all threads' K parts visible

        // ---- QK: 8 rows x 2 key cols per lane, register double-buffered ----
        u64 s2[8][2];
#pragma unroll
        for (int i = 0; i < 8; i++)
#pragma unroll
            for (int j = 0; j < 2; j++) s2[i][j] = 0ull;

        ulonglong2 qn[8], kn[2];
#pragma unroll
        for (int i = 0; i < 8; i++) qn[i] = *(const ulonglong2*)&Qs[qr[i] * 260];
        kn[0] = *(const ulonglong2*)&Ks[tx * 260];
        kn[1] = *(const ulonglong2*)&Ks[(tx + 32) * 260];

#pragma unroll 4
        for (int e = 0; e < NE; e += 4) {
            ulonglong2 qc[8], kc[2];
#pragma unroll
            for (int i = 0; i < 8; i++) qc[i] = qn[i];
            kc[0] = kn[0];
            kc[1] = kn[1];
            // prefetch next step (e=252 reads the 4-float row pad: in-bounds)
#pragma unroll
            for (int i = 0; i < 8; i++) qn[i] = *(const ulonglong2*)&Qs[qr[i] * 260 + e + 4];
            kn[0] = *(const ulonglong2*)&Ks[tx * 260 + e + 4];
            kn[1] = *(const ulonglong2*)&Ks[(tx + 32) * 260 + e + 4];
#pragma unroll
            for (int i = 0; i < 8; i++)
#pragma unroll
                for (int j = 0; j < 2; j++) {
                    ffma2(s2[i][j], qc[i].x, kc[j].x);
                    ffma2(s2[i][j], qc[i].y, kc[j].y);
                }
        }

        // ---- softmax (full-warp reductions), 8 rows per lane ----
        float p[8][2];
#pragma unroll
        for (int i = 0; i < 8; i++) {
            float s[2];
#pragma unroll
            for (int j = 0; j < 2; j++) {
                float lo, hi;
                unpack2(s2[i][j], lo, hi);
                s[j] = (lo + hi) * rscale[i];
            }
            float mt = fmaxf(s[0], s[1]);
            mt = fmaxf(mt, __shfl_xor_sync(0xffffffffu, mt, 16));
            mt = fmaxf(mt, __shfl_xor_sync(0xffffffffu, mt, 8));
            mt = fmaxf(mt, __shfl_xor_sync(0xffffffffu, mt, 4));
            mt = fmaxf(mt, __shfl_xor_sync(0xffffffffu, mt, 2));
            mt = fmaxf(mt, __shfl_xor_sync(0xffffffffu, mt, 1));
            float mn = fmaxf(m_run[i], mt);

            float sum = 0.f;
#pragma unroll
            for (int j = 0; j < 2; j++) {
                p[i][j] = __expf(s[j] - mn);
                sum += p[i][j];
            }
            sum += __shfl_xor_sync(0xffffffffu, sum, 16);
            sum += __shfl_xor_sync(0xffffffffu, sum, 8);
            sum += __shfl_xor_sync(0xffffffffu, sum, 4);
            sum += __shfl_xor_sync(0xffffffffu, sum, 2);
            sum += __shfl_xor_sync(0xffffffffu, sum, 1);

            float alpha = __expf(m_run[i] - mn);  // 0 on first tile
            l_run[i] = l_run[i] * alpha + sum;
            m_run[i] = mn;
            u64 a2 = pack2(alpha, alpha);
#pragma unroll
            for (int cc = 0; cc < 2; cc++) {
                fmul2(O2[i][cc].x, a2);
                fmul2(O2[i][cc].y, a2);
            }
        }

        // P rows wy+8i produced & consumed by warp wy only
#pragma unroll
        for (int i = 0; i < 8; i++)
#pragma unroll
            for (int j = 0; j < 2; j++) Ps[qr[i] * 68 + tx + 32 * j] = p[i][j];
        __syncwarp();

        cp_wait0();        // V(kt) resident (thread-local)
        __syncthreads();   // all V parts visible AND all warps done reading Ks

        // prefetch K(kt+1) into Ks — overlaps the PV phase
        if (kt + 1 < NS / 64) {
            const float* Kn = Kg + (size_t)(kt + 1) * 64 * NE;
            for (int i = tid; i < 64 * 64; i += 256) {
                int r = i >> 6, c = (i & 63) << 2;
                cp16(&Ks[r * 260 + c], &Kn[(size_t)r * NE + c]);
            }
            cp_commit();
        }

        // ---- PV: 8 rows x 8 out cols per lane, register double-buffered ----
        ulonglong2 vn[2];
        vn[0] = *(const ulonglong2*)&Vs[(tx << 2)];
        vn[1] = *(const ulonglong2*)&Vs[(tx << 2) + 128];
        float pn[8];
#pragma unroll
        for (int i = 0; i < 8; i++) pn[i] = Ps[qr[i] * 68];

#pragma unroll 4
        for (int j = 0; j < 64; j++) {
            ulonglong2 vc[2];
            vc[0] = vn[0];
            vc[1] = vn[1];
            u64 pp[8];
#pragma unroll
            for (int i = 0; i < 8; i++) pp[i] = pack2(pn[i], pn[i]);
            // prefetch next step (j=63 reads into Ps region: in smem bounds)
            vn[0] = *(const ulonglong2*)&Vs[(j + 1) * 260 + (tx << 2)];
            vn[1] = *(const ulonglong2*)&Vs[(j + 1) * 260 + (tx << 2) + 128];
#pragma unroll
            for (int i = 0; i < 8; i++) pn[i] = Ps[qr[i] * 68 + j + 1];
#pragma unroll
            for (int i = 0; i < 8; i++)
#pragma unroll
                for (int cc = 0; cc < 2; cc++) {
                    ffma2(O2[i][cc].x, pp[i], vc[cc].x);
                    ffma2(O2[i][cc].y, pp[i], vc[cc].y);
                }
        }
        __syncthreads();   // all warps done reading Vs

        // prefetch V(kt+1) into Vs — overlaps next tile's QK phase
        if (kt + 1 < NS / 64) {
            const float* Vn = Vg + (size_t)(kt + 1) * 64 * NE;
            for (int i = tid; i < 64 * 64; i += 256) {
                int r = i >> 6, c = (i & 63) << 2;
                cp16(&Vs[r * 260 + c], &Vn[(size_t)r * NE + c]);
            }
            cp_commit();
        }
    }

    // Epilogue: normalize (packed) and store 16B per (i,cc)
#pragma unroll
    for (int i = 0; i < 8; i++) {
        float inv = 1.0f / l_run[i];
        u64 inv2 = pack2(inv, inv);
#pragma unroll
        for (int cc = 0; cc < 2; cc++) {
            fmul2(O2[i][cc].x, inv2);
            fmul2(O2[i][cc].y, inv2);
            *(ulonglong2*)&out[(size_t)(b * NS + q0 + qr[i]) * NE + (tx << 2) + 128 * cc] =
                O2[i][cc];
        }
    }
}

// ---------------------------------------------------------------------------
extern "C" void kernel_launch(void* const* d_in, const int* in_sizes, int n_in,
                              void* d_out, int out_size) {
    (void)in_sizes; (void)n_in; (void)out_size;
    const float* x    = (const float*)d_in[0];  // [8, 2048, 256] f32
    const float* w    = (const float*)d_in[1];  // [3, 256, 256]  f32
    const int*   mask = (const int*)d_in[2];    // [8, 2048]      i32
    float* out = (float*)d_out;                 // [8, 2048, 256] f32

    dim3 g1((NB * NS) / 64, NE / 64);
    qkv_kernel<<<g1, 256>>>(x, w);

    const size_t smem = (size_t)(3 * 64 * 260 + 64 * 68 + 64) * sizeof(float);  // 217,344 B
    cudaFuncSetAttribute(attn_kernel, cudaFuncAttributeMaxDynamicSharedMemorySize,
                         (int)smem);
    dim3 g2(NS / 64, NB);
    attn_kernel<<<g2, 256, smem>>>(mask, out);
}